// round 14
// baseline (speedup 1.0000x reference)
#include <cuda_runtime.h>
#include <cuda_bf16.h>
#include <cstdint>

#define NROWS 16384
#define INF   512
#define HID   256
#define OUTF  16
#define NITER 16
#define SIGMA2 0.1f
#define L8_SCALE 8192.0f               // L stored as L * 2^13 in e4m3

// ---------------- scratch (static device globals; no allocation) ----------------
__device__ unsigned char g_L8[(size_t)NROWS * NROWS];          // 256 MB e4m3 L * 2^13
__device__ float         g_h [(size_t)NROWS * HID];            // 16 MB hidden
__device__ float         g_u [2][(size_t)NROWS * OUTF];        // fp32 u ping-pong
__device__ unsigned char g_uT8[2][(size_t)OUTF * NROWS];       // e4m3 u^T ping-pong

// ---------------- PTX helpers ----------------
__device__ __forceinline__ uint32_t smem_to_u32(const void* p) {
    uint32_t a;
    asm("{ .reg .u64 t; cvta.to.shared.u64 t, %1; cvt.u32.u64 %0, t; }" : "=r"(a) : "l"(p));
    return a;
}
#define SMEM_SWIZZLE_128B(off) ((off) ^ (((off) >> 3) & 0x70))

__device__ __forceinline__ void cp_async16(uint32_t dst, const void* src) {
    asm volatile("cp.async.cg.shared.global [%0], [%1], 16;" :: "r"(dst), "l"(src) : "memory");
}

#define LDSM_X4(r0_, r1_, r2_, r3_, addr_) \
    asm volatile("ldmatrix.sync.aligned.m8n8.x4.shared.b16 {%0,%1,%2,%3}, [%4];" \
        : "=r"(r0_), "=r"(r1_), "=r"(r2_), "=r"(r3_) : "r"(addr_))

__device__ __forceinline__ void mma16832_e4m3(float* c, uint32_t a0, uint32_t a1, uint32_t a2,
                                              uint32_t a3, uint32_t b0, uint32_t b1) {
    asm volatile(
        "mma.sync.aligned.m16n8k32.row.col.f32.e4m3.e4m3.f32 "
        "{%0,%1,%2,%3}, {%4,%5,%6,%7}, {%8,%9}, {%0,%1,%2,%3};"
        : "+f"(c[0]), "+f"(c[1]), "+f"(c[2]), "+f"(c[3])
        : "r"(a0), "r"(a1), "r"(a2), "r"(a3), "r"(b0), "r"(b1));
}

// pack two floats -> two e4m3 bytes (lo = x, hi = y)
__device__ __forceinline__ uint16_t f2_to_e4m3x2(float x, float y) {
    uint16_t p;
    asm("cvt.rn.satfinite.e4m3x2.f32 %0, %1, %2;" : "=h"(p) : "f"(y), "f"(x));
    return p;
}
__device__ __forceinline__ unsigned char f_to_e4m3(float v) {
    return (unsigned char)(f2_to_e4m3x2(v, 0.f) & 0xFF);
}

// ============================================================================
// prep_kernel: heterogeneous grid fusing two INDEPENDENT jobs.
//   blockIdx.x % 3 == 0  (512 blocks): L fp32 -> e4m3 * 2^13
//   else                 (1024 blocks): one 64x64 tile of h = elu(f@W1 + b1)
// ============================================================================
#define PREP_CONV_BLOCKS 512
#define PREP_HID_BLOCKS  1024
#define PREP_BLOCKS      (PREP_CONV_BLOCKS + PREP_HID_BLOCKS)

__global__ __launch_bounds__(256) void prep_kernel(const float* __restrict__ L,
                                                   const float* __restrict__ f,
                                                   const float* __restrict__ W1,
                                                   const float* __restrict__ b1) {
    __shared__ float As[16][68];
    __shared__ float Bs[16][68];
    int bid = blockIdx.x;

    if (bid % 3 == 0) {
        int conv_id = bid / 3;
        int tid256 = threadIdx.y * 16 + threadIdx.x;
        size_t total8 = (size_t)NROWS * NROWS / 8;
        size_t stride = (size_t)PREP_CONV_BLOCKS * 256;
        const float4* L4 = (const float4*)L;
        uint2* out8 = (uint2*)g_L8;
        for (size_t i = (size_t)conv_id * 256 + tid256; i < total8; i += stride) {
            float4 v0 = L4[i * 2];
            float4 v1 = L4[i * 2 + 1];
            uint32_t q01 = f2_to_e4m3x2(v0.x * L8_SCALE, v0.y * L8_SCALE)
                         | ((uint32_t)f2_to_e4m3x2(v0.z * L8_SCALE, v0.w * L8_SCALE) << 16);
            uint32_t q23 = f2_to_e4m3x2(v1.x * L8_SCALE, v1.y * L8_SCALE)
                         | ((uint32_t)f2_to_e4m3x2(v1.z * L8_SCALE, v1.w * L8_SCALE) << 16);
            out8[i] = make_uint2(q01, q23);
        }
        return;
    }

    int hid_id = bid - bid / 3 - 1;
    int tx = threadIdx.x, ty = threadIdx.y;
    int tid = ty * 16 + tx;
    int col0 = (hid_id & 3) * 64;
    int row0 = (hid_id >> 2) * 64;
    float acc[4][4] = {};
    for (int k0 = 0; k0 < INF; k0 += 16) {
        #pragma unroll
        for (int it = 0; it < 4; it++) {
            int r  = (tid >> 4) + it * 16;
            int kk = tid & 15;
            As[kk][r] = f[(size_t)(row0 + r) * INF + k0 + kk];
        }
        #pragma unroll
        for (int it = 0; it < 4; it++) {
            int kk = (tid >> 6) + it * 4;
            int c  = tid & 63;
            Bs[kk][c] = W1[(size_t)(k0 + kk) * HID + col0 + c];
        }
        __syncthreads();
        #pragma unroll
        for (int kk = 0; kk < 16; kk++) {
            float4 a4 = *(const float4*)&As[kk][ty * 4];
            float4 b4 = *(const float4*)&Bs[kk][tx * 4];
            float av[4] = {a4.x, a4.y, a4.z, a4.w};
            float bv[4] = {b4.x, b4.y, b4.z, b4.w};
            #pragma unroll
            for (int i = 0; i < 4; i++)
                #pragma unroll
                for (int j = 0; j < 4; j++)
                    acc[i][j] += av[i] * bv[j];
        }
        __syncthreads();
    }
    #pragma unroll
    for (int i = 0; i < 4; i++) {
        int r = row0 + ty * 4 + i;
        #pragma unroll
        for (int j = 0; j < 4; j++) {
            int c = col0 + tx * 4 + j;
            float v = acc[i][j] + b1[c];
            v = v > 0.0f ? v : expm1f(v);
            g_h[(size_t)r * HID + c] = v;
        }
    }
}

// ---------------- u0 = f@Ws + bs + h@W2 + b2 (writes fp32 u + fp8 u^T) ----------------
__global__ __launch_bounds__(256) void u0_kernel(const float* __restrict__ f,
                                                 const float* __restrict__ Ws,
                                                 const float* __restrict__ bs,
                                                 const float* __restrict__ W2,
                                                 const float* __restrict__ b2) {
    __shared__ float sWs[INF * OUTF];
    __shared__ float sW2[HID * OUTF];
    int tid = threadIdx.x;
    for (int i = tid; i < INF * OUTF; i += 256) sWs[i] = Ws[i];
    for (int i = tid; i < HID * OUTF; i += 256) sW2[i] = W2[i];
    __syncthreads();
    int c   = tid & 15;
    int row = blockIdx.x * 16 + (tid >> 4);
    float acc = bs[c] + b2[c];
    const float4* f4 = (const float4*)(f + (size_t)row * INF);
    #pragma unroll 4
    for (int k4 = 0; k4 < INF / 4; k4++) {
        float4 v = f4[k4];
        int k = k4 * 4;
        acc += v.x * sWs[k * 16 + c] + v.y * sWs[(k + 1) * 16 + c]
             + v.z * sWs[(k + 2) * 16 + c] + v.w * sWs[(k + 3) * 16 + c];
    }
    const float4* h4 = (const float4*)(g_h + (size_t)row * HID);
    #pragma unroll 4
    for (int k4 = 0; k4 < HID / 4; k4++) {
        float4 v = h4[k4];
        int k = k4 * 4;
        acc += v.x * sW2[k * 16 + c] + v.y * sW2[(k + 1) * 16 + c]
             + v.z * sW2[(k + 2) * 16 + c] + v.w * sW2[(k + 3) * 16 + c];
    }
    g_u[0][(size_t)row * OUTF + c] = acc;
    g_uT8[0][(size_t)c * NROWS + row] = f_to_e4m3(acc);
}

// ---- pipeline geometry ----
#define NSTG 5
#define A_SUB 8192                     // 64 rows x 128B
#define B_SUB 2048                     // 16 rows x 128B
#define STG_BYTES (2 * A_SUB + 2 * B_SUB)   // 20480
#define DIFF_SMEM (NSTG * STG_BYTES)        // 102400
#define KCH8 256
#define NCHUNK8 (NROWS / KCH8)         // 64

// ============================================================================
// diff8_kernel (e4m3, split-k): 256 CTAs x 256 threads (8 warps).
// D[64,16] = (L*2^13)[rows,:] @ u. Warps 0-3 compute k-sub-tile 0,
// warps 4-7 compute k-sub-tile 1; partials reduced through smem at the end.
// Halves per-warp LDSM/QMMA/ALU issue density so cp.async issue isn't starved;
// 4 warps/SMSP for latency hiding. Same 20KB stages / NSTG=5 / coalesced maps.
// ============================================================================
__global__ __launch_bounds__(256, 2) void diff8_kernel(int sel_in, float* __restrict__ final_out) {
    extern __shared__ char smem[];
    uint32_t sbase = smem_to_u32(smem);
    int tid = threadIdx.x;
    int w = tid >> 5, lane = tid & 31;
    int wk = w >> 2;                   // k-half: 0 or 1
    int wm = w & 3;                    // 16-row group within the 64-row tile
    int r0 = blockIdx.x * 64;

    const unsigned char* Abase = g_L8 + (size_t)r0 * NROWS;
    const unsigned char* uT    = g_uT8[sel_in];

    // A loads: 8 lanes per row, rows (tid>>3) + 32*i, both sub-tiles per row.
    const int l_row = tid >> 3;        // 0..31
    const int l_seg = tid & 7;         // 0..7
    // B loads: 16 lanes per row (256B contiguous), rows tid>>4.
    const int b_row = tid >> 4;        // 0..15
    const int b_sub = (tid >> 3) & 1;  // sub-tile select
    const int b_seg = tid & 7;

    auto load_chunk = [&](int j, int s) {
        uint32_t base = sbase + (uint32_t)s * STG_BYTES;
        int k0 = j * KCH8;   // bytes
        #pragma unroll
        for (int i = 0; i < 2; i++) {
            int row = l_row + 32 * i;
            const unsigned char* src = Abase + (size_t)row * NROWS + k0 + l_seg * 16;
            uint32_t off = SMEM_SWIZZLE_128B((uint32_t)(row * 128 + l_seg * 16));
            cp_async16(base + off, src);               // sub-tile 0: k[0..127]
            cp_async16(base + A_SUB + off, src + 128); // sub-tile 1: k[128..255]
        }
        const unsigned char* bsrc = uT + (size_t)b_row * NROWS + k0 + b_sub * 128 + b_seg * 16;
        uint32_t boff = SMEM_SWIZZLE_128B((uint32_t)(b_row * 128 + b_seg * 16));
        cp_async16(base + 2 * A_SUB + (uint32_t)b_sub * B_SUB + boff, bsrc);
    };

    #pragma unroll
    for (int i = 0; i < NSTG - 1; i++) {
        load_chunk(i, i);
        asm volatile("cp.async.commit_group;" ::: "memory");
    }

    const int a_r = lane & 15;
    const int a_h = (lane >> 4) * 16;
    const int b_n = (lane & 7) + ((lane & 16) ? 8 : 0);
    const int b_h = ((lane >> 3) & 1) * 16;

    float acc0[4] = {0.f, 0.f, 0.f, 0.f};
    float acc1[4] = {0.f, 0.f, 0.f, 0.f};

    for (int i = 0; i < NCHUNK8; i++) {
        int s = i % NSTG;
        asm volatile("cp.async.wait_group %0;" :: "n"(NSTG - 2) : "memory");
        __syncthreads();

        int j = i + NSTG - 1;
        if (j < NCHUNK8) load_chunk(j, j % NSTG);
        asm volatile("cp.async.commit_group;" ::: "memory");

        uint32_t base = sbase + (uint32_t)s * STG_BYTES;
        uint32_t Ab = base + (uint32_t)wk * A_SUB;                 // this warp's k-half
        uint32_t Bb = base + 2 * A_SUB + (uint32_t)wk * B_SUB;
        #pragma unroll
        for (int kk = 0; kk < 64; kk += 16) {     // pseudo-b16 units; 32 real k each
            uint32_t aoff = (uint32_t)((wm * 16 + a_r) * 128 + kk * 2 + a_h);
            uint32_t a0, a1, a2, a3;
            LDSM_X4(a0, a1, a2, a3, Ab + SMEM_SWIZZLE_128B(aoff));
            uint32_t boff = (uint32_t)(b_n * 128 + kk * 2 + b_h);
            uint32_t b0, b1, b2, b3;
            LDSM_X4(b0, b1, b2, b3, Bb + SMEM_SWIZZLE_128B(boff));
            mma16832_e4m3(acc0, a0, a1, a2, a3, b0, b1);
            mma16832_e4m3(acc1, a0, a1, a2, a3, b2, b3);
        }
    }

    // ---- split-k reduction: warps 4-7 hand partials to warps 0-3 via smem ----
    __syncthreads();                   // all compute done; no cp.async in flight
    float* red = (float*)smem;         // 4 warps x 32 lanes x 8 floats = 4 KB
    if (wk == 1) {
        float* dst = red + (wm * 32 + lane) * 8;
        dst[0] = acc0[0]; dst[1] = acc0[1]; dst[2] = acc0[2]; dst[3] = acc0[3];
        dst[4] = acc1[0]; dst[5] = acc1[1]; dst[6] = acc1[2]; dst[7] = acc1[3];
    }
    __syncthreads();
    if (wk == 1) return;
    {
        const float* src = red + (wm * 32 + lane) * 8;
        acc0[0] += src[0]; acc0[1] += src[1]; acc0[2] += src[2]; acc0[3] += src[3];
        acc1[0] += src[4]; acc1[1] += src[5]; acc1[2] += src[6]; acc1[3] += src[7];
    }

    // ---- epilogue: u_new = u - (sigma2/2^13) * acc ----
    const float s2 = SIGMA2 / L8_SCALE;
    int gr = lane >> 2;
    int gc = (lane & 3) * 2;
    int rowA = r0 + wm * 16 + gr;
    int rowB = rowA + 8;

    const float* uA = g_u[sel_in] + (size_t)rowA * OUTF;
    const float* uB = g_u[sel_in] + (size_t)rowB * OUTF;
    float rA[4], rB[4];
    rA[0] = uA[gc]     - s2 * acc0[0];
    rA[1] = uA[gc + 1] - s2 * acc0[1];
    rA[2] = uA[gc + 8] - s2 * acc1[0];
    rA[3] = uA[gc + 9] - s2 * acc1[1];
    rB[0] = uB[gc]     - s2 * acc0[2];
    rB[1] = uB[gc + 1] - s2 * acc0[3];
    rB[2] = uB[gc + 8] - s2 * acc1[2];
    rB[3] = uB[gc + 9] - s2 * acc1[3];

    if (final_out) {
        *(float2*)(final_out + (size_t)rowA * OUTF + gc)     = make_float2(rA[0], rA[1]);
        *(float2*)(final_out + (size_t)rowA * OUTF + gc + 8) = make_float2(rA[2], rA[3]);
        *(float2*)(final_out + (size_t)rowB * OUTF + gc)     = make_float2(rB[0], rB[1]);
        *(float2*)(final_out + (size_t)rowB * OUTF + gc + 8) = make_float2(rB[2], rB[3]);
    } else {
        int so = sel_in ^ 1;
        float* uo = g_u[so];
        *(float2*)(uo + (size_t)rowA * OUTF + gc)     = make_float2(rA[0], rA[1]);
        *(float2*)(uo + (size_t)rowA * OUTF + gc + 8) = make_float2(rA[2], rA[3]);
        *(float2*)(uo + (size_t)rowB * OUTF + gc)     = make_float2(rB[0], rB[1]);
        *(float2*)(uo + (size_t)rowB * OUTF + gc + 8) = make_float2(rB[2], rB[3]);
        unsigned char* t8 = g_uT8[so];
        #pragma unroll
        for (int q = 0; q < 4; q++) {
            int cA = (q < 2) ? gc + q : gc + 6 + q;   // gc,gc+1,gc+8,gc+9
            t8[(size_t)cA * NROWS + rowA] = f_to_e4m3(rA[q]);
            t8[(size_t)cA * NROWS + rowB] = f_to_e4m3(rB[q]);
        }
    }
}

// ---------------- launch ----------------
extern "C" void kernel_launch(void* const* d_in, const int* in_sizes, int n_in,
                              void* d_out, int out_size) {
    const float* f  = (const float*)d_in[0];
    const float* L  = (const float*)d_in[1];
    const float* W1 = (const float*)d_in[2];
    const float* b1 = (const float*)d_in[3];
    const float* W2 = (const float*)d_in[4];
    const float* b2 = (const float*)d_in[5];
    const float* Ws = (const float*)d_in[6];
    const float* bs = (const float*)d_in[7];
    float* out = (float*)d_out;
    (void)in_sizes; (void)n_in; (void)out_size;

    cudaFuncSetAttribute(diff8_kernel, cudaFuncAttributeMaxDynamicSharedMemorySize, DIFF_SMEM);

    prep_kernel<<<PREP_BLOCKS, dim3(16, 16)>>>(L, f, W1, b1);
    u0_kernel<<<NROWS / 16, 256>>>(f, Ws, bs, W2, b2);

    for (int it = 0; it < NITER; it++) {
        int sel = it & 1;
        float* fo = (it == NITER - 1) ? out : nullptr;
        diff8_kernel<<<NROWS / 64, 256, DIFF_SMEM>>>(sel, fo);
    }
}

// round 15
// speedup vs baseline: 1.0636x; 1.0636x over previous
#include <cuda_runtime.h>
#include <cuda_bf16.h>
#include <cstdint>

#define NROWS 16384
#define INF   512
#define HID   256
#define OUTF  16
#define NITER 16
#define SIGMA2 0.1f
#define L8_SCALE 8192.0f               // L stored as L * 2^13 in e4m3

// ---------------- scratch (static device globals; no allocation) ----------------
__device__ unsigned char g_L8[(size_t)NROWS * NROWS];          // 256 MB e4m3 L * 2^13
__device__ float         g_h [(size_t)NROWS * HID];            // 16 MB hidden
__device__ float         g_u [2][(size_t)NROWS * OUTF];        // fp32 u ping-pong
__device__ unsigned char g_uT8[2][(size_t)OUTF * NROWS];       // e4m3 u^T ping-pong
__device__ unsigned int  g_bar;                                // grid barrier counter

// ---------------- PTX helpers ----------------
__device__ __forceinline__ uint32_t smem_to_u32(const void* p) {
    uint32_t a;
    asm("{ .reg .u64 t; cvta.to.shared.u64 t, %1; cvt.u32.u64 %0, t; }" : "=r"(a) : "l"(p));
    return a;
}
#define SMEM_SWIZZLE_128B(off) ((off) ^ (((off) >> 3) & 0x70))

__device__ __forceinline__ void cp_async16(uint32_t dst, const void* src) {
    asm volatile("cp.async.cg.shared.global [%0], [%1], 16;" :: "r"(dst), "l"(src) : "memory");
}

#define LDSM_X4(r0_, r1_, r2_, r3_, addr_) \
    asm volatile("ldmatrix.sync.aligned.m8n8.x4.shared.b16 {%0,%1,%2,%3}, [%4];" \
        : "=r"(r0_), "=r"(r1_), "=r"(r2_), "=r"(r3_) : "r"(addr_))

__device__ __forceinline__ void mma16832_e4m3(float* c, uint32_t a0, uint32_t a1, uint32_t a2,
                                              uint32_t a3, uint32_t b0, uint32_t b1) {
    asm volatile(
        "mma.sync.aligned.m16n8k32.row.col.f32.e4m3.e4m3.f32 "
        "{%0,%1,%2,%3}, {%4,%5,%6,%7}, {%8,%9}, {%0,%1,%2,%3};"
        : "+f"(c[0]), "+f"(c[1]), "+f"(c[2]), "+f"(c[3])
        : "r"(a0), "r"(a1), "r"(a2), "r"(a3), "r"(b0), "r"(b1));
}

// pack two floats -> two e4m3 bytes (lo = x, hi = y)
__device__ __forceinline__ uint16_t f2_to_e4m3x2(float x, float y) {
    uint16_t p;
    asm("cvt.rn.satfinite.e4m3x2.f32 %0, %1, %2;" : "=h"(p) : "f"(y), "f"(x));
    return p;
}
__device__ __forceinline__ unsigned char f_to_e4m3(float v) {
    return (unsigned char)(f2_to_e4m3x2(v, 0.f) & 0xFF);
}

// ============================================================================
// prep_kernel: heterogeneous grid fusing two INDEPENDENT jobs.
//   blockIdx.x % 3 == 0  (512 blocks): L fp32 -> e4m3 * 2^13
//   else                 (1024 blocks): one 64x64 tile of h = elu(f@W1 + b1)
// ============================================================================
#define PREP_CONV_BLOCKS 512
#define PREP_HID_BLOCKS  1024
#define PREP_BLOCKS      (PREP_CONV_BLOCKS + PREP_HID_BLOCKS)

__global__ __launch_bounds__(256) void prep_kernel(const float* __restrict__ L,
                                                   const float* __restrict__ f,
                                                   const float* __restrict__ W1,
                                                   const float* __restrict__ b1) {
    __shared__ float As[16][68];
    __shared__ float Bs[16][68];
    int bid = blockIdx.x;

    if (bid % 3 == 0) {
        int conv_id = bid / 3;
        int tid256 = threadIdx.y * 16 + threadIdx.x;
        size_t total8 = (size_t)NROWS * NROWS / 8;
        size_t stride = (size_t)PREP_CONV_BLOCKS * 256;
        const float4* L4 = (const float4*)L;
        uint2* out8 = (uint2*)g_L8;
        for (size_t i = (size_t)conv_id * 256 + tid256; i < total8; i += stride) {
            float4 v0 = L4[i * 2];
            float4 v1 = L4[i * 2 + 1];
            uint32_t q01 = f2_to_e4m3x2(v0.x * L8_SCALE, v0.y * L8_SCALE)
                         | ((uint32_t)f2_to_e4m3x2(v0.z * L8_SCALE, v0.w * L8_SCALE) << 16);
            uint32_t q23 = f2_to_e4m3x2(v1.x * L8_SCALE, v1.y * L8_SCALE)
                         | ((uint32_t)f2_to_e4m3x2(v1.z * L8_SCALE, v1.w * L8_SCALE) << 16);
            out8[i] = make_uint2(q01, q23);
        }
        return;
    }

    int hid_id = bid - bid / 3 - 1;
    int tx = threadIdx.x, ty = threadIdx.y;
    int tid = ty * 16 + tx;
    int col0 = (hid_id & 3) * 64;
    int row0 = (hid_id >> 2) * 64;
    float acc[4][4] = {};
    for (int k0 = 0; k0 < INF; k0 += 16) {
        #pragma unroll
        for (int it = 0; it < 4; it++) {
            int r  = (tid >> 4) + it * 16;
            int kk = tid & 15;
            As[kk][r] = f[(size_t)(row0 + r) * INF + k0 + kk];
        }
        #pragma unroll
        for (int it = 0; it < 4; it++) {
            int kk = (tid >> 6) + it * 4;
            int c  = tid & 63;
            Bs[kk][c] = W1[(size_t)(k0 + kk) * HID + col0 + c];
        }
        __syncthreads();
        #pragma unroll
        for (int kk = 0; kk < 16; kk++) {
            float4 a4 = *(const float4*)&As[kk][ty * 4];
            float4 b4 = *(const float4*)&Bs[kk][tx * 4];
            float av[4] = {a4.x, a4.y, a4.z, a4.w};
            float bv[4] = {b4.x, b4.y, b4.z, b4.w};
            #pragma unroll
            for (int i = 0; i < 4; i++)
                #pragma unroll
                for (int j = 0; j < 4; j++)
                    acc[i][j] += av[i] * bv[j];
        }
        __syncthreads();
    }
    #pragma unroll
    for (int i = 0; i < 4; i++) {
        int r = row0 + ty * 4 + i;
        #pragma unroll
        for (int j = 0; j < 4; j++) {
            int c = col0 + tx * 4 + j;
            float v = acc[i][j] + b1[c];
            v = v > 0.0f ? v : expm1f(v);
            g_h[(size_t)r * HID + c] = v;
        }
    }
}

// ---------------- u0 = f@Ws + bs + h@W2 + b2 (writes fp32 u + fp8 u^T) ----------------
__global__ __launch_bounds__(256) void u0_kernel(const float* __restrict__ f,
                                                 const float* __restrict__ Ws,
                                                 const float* __restrict__ bs,
                                                 const float* __restrict__ W2,
                                                 const float* __restrict__ b2) {
    __shared__ float sWs[INF * OUTF];
    __shared__ float sW2[HID * OUTF];
    int tid = threadIdx.x;
    if (blockIdx.x == 0 && tid == 0) g_bar = 0;     // reset grid barrier each launch
    for (int i = tid; i < INF * OUTF; i += 256) sWs[i] = Ws[i];
    for (int i = tid; i < HID * OUTF; i += 256) sW2[i] = W2[i];
    __syncthreads();
    int c   = tid & 15;
    int row = blockIdx.x * 16 + (tid >> 4);
    float acc = bs[c] + b2[c];
    const float4* f4 = (const float4*)(f + (size_t)row * INF);
    #pragma unroll 4
    for (int k4 = 0; k4 < INF / 4; k4++) {
        float4 v = f4[k4];
        int k = k4 * 4;
        acc += v.x * sWs[k * 16 + c] + v.y * sWs[(k + 1) * 16 + c]
             + v.z * sWs[(k + 2) * 16 + c] + v.w * sWs[(k + 3) * 16 + c];
    }
    const float4* h4 = (const float4*)(g_h + (size_t)row * HID);
    #pragma unroll 4
    for (int k4 = 0; k4 < HID / 4; k4++) {
        float4 v = h4[k4];
        int k = k4 * 4;
        acc += v.x * sW2[k * 16 + c] + v.y * sW2[(k + 1) * 16 + c]
             + v.z * sW2[(k + 2) * 16 + c] + v.w * sW2[(k + 3) * 16 + c];
    }
    g_u[0][(size_t)row * OUTF + c] = acc;
    g_uT8[0][(size_t)c * NROWS + row] = f_to_e4m3(acc);
}

// ---- pipeline geometry ----
#define NSTG 5
#define A_SUB 8192                     // 64 rows x 128B
#define B_SUB 2048                     // 16 rows x 128B
#define STG_BYTES (2 * A_SUB + 2 * B_SUB)   // 20480
#define DIFF_SMEM (NSTG * STG_BYTES)        // 102400
#define KCH8 256
#define NCHUNK8 (NROWS / KCH8)         // 64

// ============================================================================
// diff8_persist: ALL 16 diffusion steps in one persistent kernel.
// 256 CTAs x 128 threads (one resident wave: 2 CTAs/SM x 148 SMs = 296 slots).
// Per step identical to the proven R13 pipeline (64-row tile, 256B/row/chunk,
// two 128B SW128 sub-tiles, coalesced cp.async, NSTG=5 single-barrier).
// Across steps: A (L, 99% of traffic) is step-invariant, so iterations 60..63
// prefetch next step's chunks 0..3 A-halves; after a grid barrier only the 4
// small B loads (u^T, L2-resident) are issued -> DRAM never drains between
// steps. Stage ring uses continuous rotating counters across steps.
// ============================================================================
__global__ __launch_bounds__(128, 2) void diff8_persist(float* __restrict__ final_out) {
    extern __shared__ char smem[];
    uint32_t sbase = smem_to_u32(smem);
    int tid = threadIdx.x;
    int wid = tid >> 5, lane = tid & 31;
    int r0 = blockIdx.x * 64;

    const unsigned char* Abase = g_L8 + (size_t)r0 * NROWS;

    const int l_row = tid >> 3;        // 0..15
    const int l_seg = tid & 7;         // 0..7

    auto load_A = [&](int c, int s) {
        uint32_t base = sbase + (uint32_t)s * STG_BYTES;
        int k0 = c * KCH8;   // bytes
        #pragma unroll
        for (int i = 0; i < 4; i++) {
            int row = l_row + 16 * i;
            const unsigned char* src = Abase + (size_t)row * NROWS + k0 + l_seg * 16;
            uint32_t off = SMEM_SWIZZLE_128B((uint32_t)(row * 128 + l_seg * 16));
            cp_async16(base + off, src);               // sub-tile 0: k[0..127]
            cp_async16(base + A_SUB + off, src + 128); // sub-tile 1: k[128..255]
        }
    };
    auto load_B = [&](const unsigned char* uT, int c, int s) {
        uint32_t base = sbase + (uint32_t)s * STG_BYTES + 2 * A_SUB;
        int k0 = c * KCH8;
        const unsigned char* bsrc = uT + (size_t)l_row * NROWS + k0 + l_seg * 16;
        uint32_t boff = SMEM_SWIZZLE_128B((uint32_t)(l_row * 128 + l_seg * 16));
        cp_async16(base + boff, bsrc);
        cp_async16(base + B_SUB + boff, bsrc + 128);
    };

    // prologue: chunks 0..3 of step 0 (A + B combined)
    int s_load = 0;
    {
        const unsigned char* uT0 = g_uT8[0];
        #pragma unroll
        for (int p = 0; p < NSTG - 1; p++) {
            load_A(p, s_load);
            load_B(uT0, p, s_load);
            asm volatile("cp.async.commit_group;" ::: "memory");
            if (++s_load == NSTG) s_load = 0;
        }
    }

    const int a_r = lane & 15;
    const int a_h = (lane >> 4) * 16;
    const int b_n = (lane & 7) + ((lane & 16) ? 8 : 0);
    const int b_h = ((lane >> 3) & 1) * 16;
    const float s2 = SIGMA2 / L8_SCALE;

    int s_comp = 0;

    for (int t = 0; t < NITER; t++) {
        int sel = t & 1;
        const unsigned char* uT = g_uT8[sel];
        float acc0[4] = {0.f, 0.f, 0.f, 0.f};
        float acc1[4] = {0.f, 0.f, 0.f, 0.f};

        for (int i = 0; i < NCHUNK8; i++) {
            asm volatile("cp.async.wait_group %0;" :: "n"(NSTG - 2) : "memory");
            __syncthreads();   // stage being refilled was consumed last iteration

            int j = i + NSTG - 1;
            if (j < NCHUNK8) {
                load_A(j, s_load);
                load_B(uT, j, s_load);
            } else if (t + 1 < NITER) {
                load_A(j - NCHUNK8, s_load);   // next step's A prefetch (A is step-invariant)
            }
            asm volatile("cp.async.commit_group;" ::: "memory");
            if (++s_load == NSTG) s_load = 0;

            uint32_t base = sbase + (uint32_t)s_comp * STG_BYTES;
            #pragma unroll
            for (int sub = 0; sub < 2; sub++) {
                uint32_t Ab = base + (uint32_t)sub * A_SUB;
                uint32_t Bb = base + 2 * A_SUB + (uint32_t)sub * B_SUB;
                #pragma unroll
                for (int kk = 0; kk < 64; kk += 16) {   // pseudo-b16 units; 32 real k each
                    uint32_t aoff = (uint32_t)((wid * 16 + a_r) * 128 + kk * 2 + a_h);
                    uint32_t a0, a1, a2, a3;
                    LDSM_X4(a0, a1, a2, a3, Ab + SMEM_SWIZZLE_128B(aoff));
                    uint32_t boff = (uint32_t)(b_n * 128 + kk * 2 + b_h);
                    uint32_t b0, b1, b2, b3;
                    LDSM_X4(b0, b1, b2, b3, Bb + SMEM_SWIZZLE_128B(boff));
                    mma16832_e4m3(acc0, a0, a1, a2, a3, b0, b1);
                    mma16832_e4m3(acc1, a0, a1, a2, a3, b2, b3);
                }
            }
            if (++s_comp == NSTG) s_comp = 0;
        }

        // ---- epilogue: u_new = u - (sigma2/2^13) * acc ----
        {
            int gr = lane >> 2;
            int gc = (lane & 3) * 2;
            int rowA = r0 + wid * 16 + gr;
            int rowB = rowA + 8;

            const float* uA = g_u[sel] + (size_t)rowA * OUTF;
            const float* uB = g_u[sel] + (size_t)rowB * OUTF;
            float rA[4], rB[4];
            rA[0] = uA[gc]     - s2 * acc0[0];
            rA[1] = uA[gc + 1] - s2 * acc0[1];
            rA[2] = uA[gc + 8] - s2 * acc1[0];
            rA[3] = uA[gc + 9] - s2 * acc1[1];
            rB[0] = uB[gc]     - s2 * acc0[2];
            rB[1] = uB[gc + 1] - s2 * acc0[3];
            rB[2] = uB[gc + 8] - s2 * acc1[2];
            rB[3] = uB[gc + 9] - s2 * acc1[3];

            if (t == NITER - 1) {
                *(float2*)(final_out + (size_t)rowA * OUTF + gc)     = make_float2(rA[0], rA[1]);
                *(float2*)(final_out + (size_t)rowA * OUTF + gc + 8) = make_float2(rA[2], rA[3]);
                *(float2*)(final_out + (size_t)rowB * OUTF + gc)     = make_float2(rB[0], rB[1]);
                *(float2*)(final_out + (size_t)rowB * OUTF + gc + 8) = make_float2(rB[2], rB[3]);
            } else {
                int so = sel ^ 1;
                float* uo = g_u[so];
                *(float2*)(uo + (size_t)rowA * OUTF + gc)     = make_float2(rA[0], rA[1]);
                *(float2*)(uo + (size_t)rowA * OUTF + gc + 8) = make_float2(rA[2], rA[3]);
                *(float2*)(uo + (size_t)rowB * OUTF + gc)     = make_float2(rB[0], rB[1]);
                *(float2*)(uo + (size_t)rowB * OUTF + gc + 8) = make_float2(rB[2], rB[3]);
                unsigned char* t8 = g_uT8[so];
                #pragma unroll
                for (int q = 0; q < 4; q++) {
                    int cA = (q < 2) ? gc + q : gc + 6 + q;   // gc,gc+1,gc+8,gc+9
                    t8[(size_t)cA * NROWS + rowA] = f_to_e4m3(rA[q]);
                    t8[(size_t)cA * NROWS + rowB] = f_to_e4m3(rB[q]);
                }
            }
        }

        // ---- grid barrier + B loads for next step's prefetched chunks ----
        if (t + 1 < NITER) {
            __threadfence();           // release: u^T stores visible GPU-wide
            __syncthreads();           // all threads' stores + fences done
            if (tid == 0) {
                unsigned target = 256u * (unsigned)(t + 1);
                atomicAdd(&g_bar, 1u);
                while (*(volatile unsigned*)&g_bar < target) { __nanosleep(64); }
            }
            __syncthreads();
            __threadfence();           // acquire: order subsequent B reads after spin

            const unsigned char* uTn = g_uT8[sel ^ 1];
            #pragma unroll
            for (int c = 0; c < 4; c++) {
                int s = s_load + 1 + c; if (s >= NSTG) s -= NSTG;  // stage holding chunk c's A
                load_B(uTn, c, s);
                asm volatile("cp.async.commit_group;" ::: "memory");
            }
        }
    }
}

// ---------------- launch ----------------
extern "C" void kernel_launch(void* const* d_in, const int* in_sizes, int n_in,
                              void* d_out, int out_size) {
    const float* f  = (const float*)d_in[0];
    const float* L  = (const float*)d_in[1];
    const float* W1 = (const float*)d_in[2];
    const float* b1 = (const float*)d_in[3];
    const float* W2 = (const float*)d_in[4];
    const float* b2 = (const float*)d_in[5];
    const float* Ws = (const float*)d_in[6];
    const float* bs = (const float*)d_in[7];
    float* out = (float*)d_out;
    (void)in_sizes; (void)n_in; (void)out_size;

    cudaFuncSetAttribute(diff8_persist, cudaFuncAttributeMaxDynamicSharedMemorySize, DIFF_SMEM);

    prep_kernel<<<PREP_BLOCKS, dim3(16, 16)>>>(L, f, W1, b1);
    u0_kernel<<<NROWS / 16, 256>>>(f, Ws, bs, W2, b2);
    diff8_persist<<<NROWS / 64, 128, DIFF_SMEM>>>(out);
}